// round 14
// baseline (speedup 1.0000x reference)
#include <cuda_runtime.h>
#include <cstdint>
#include <cstddef>

// Problem constants (fixed by setup_inputs)
#define NN 4
#define H0 60
#define W0 80
#define H1 60
#define W1 80
#define LL (H0*W0)     // 4800 rows
#define SS (H1*W1)     // 4800 cols
#define NL (NN*LL)
#define THRV 0.2f
#define BR 2

#define TPB 512
#define NW (TPB/32)        // 16 warps
#define NQ (SS/4)          // 1200 float4 per row
#define ROWB (SS*4)        // 19200 bytes per row
#define RPS 2              // rows per work unit (stage)
#define STAGEB (RPS*ROWB)  // 38400
#define DEPTH 5            // pipeline stages
#define NCTA 148           // 1 CTA per SM, all co-resident
#define TAILQ (NQ - 2*TPB) // 176: threads with a 3rd float4

#define NSTAGES_PER_N 2400          // 4800 rows / 2
#define NUNITS (NN*NSTAGES_PER_N)   // 9600 work units
#define TICKETS (NUNITS + NCTA)     // 9748 tickets consumed per launch, exactly
#define PH3ROWS 130                 // ceil(19200/148)
#define RESCAN_K 10                 // ceil(4800/512)

// smem layout (dynamic)
#define SM_TILES 0                        // DEPTH*STAGEB = 192000
#define SM_PMAX  (DEPTH*STAGEB)           // 10 rows x 16 warps
#define SM_PCNT  (SM_PMAX + DEPTH*RPS*NW*4)
#define SM_PIDX  (SM_PCNT + DEPTH*RPS*NW*4)
#define SM_MBAR  (SM_PIDX + DEPTH*RPS*NW*4)
#define SMEM_REQ 194048

// Scratch (no allocations allowed).
// g_colmax: zero at launch entry (module init on first run; zeroed by phase 4
//   of the previous run afterwards) -> deterministic across graph replays.
// g_q / g_bar: MONOTONIC ticket counters, never reset; each launch consumes a
//   fixed number of tickets (9748 work, 2*148 barrier) -> replay-safe.
__device__ unsigned g_colmax[NN*SS];
__device__ float    g_rowmax[NL];
__device__ int      g_rowj[NL];
__device__ int      g_rowcnt[NL];
__device__ int      g_q;
__device__ int      g_bar;

__device__ __forceinline__ uint32_t smem_u32(const void* p) {
    uint32_t a;
    asm("{ .reg .u64 t; cvta.to.shared.u64 t, %1; cvt.u32.u64 %0, t; }" : "=r"(a) : "l"(p));
    return a;
}
__device__ __forceinline__ void mbar_init(uint32_t m, uint32_t cnt) {
    asm volatile("mbarrier.init.shared.b64 [%0], %1;" :: "r"(m), "r"(cnt) : "memory");
}
__device__ __forceinline__ void mbar_expect_tx(uint32_t m, uint32_t bytes) {
    asm volatile("mbarrier.arrive.expect_tx.shared.b64 _, [%0], %1;" :: "r"(m), "r"(bytes) : "memory");
}
__device__ __forceinline__ void bulk_ldg(uint32_t dst, const void* src, uint32_t bytes, uint32_t mbar) {
    asm volatile("cp.async.bulk.shared::cluster.global.mbarrier::complete_tx::bytes [%0], [%1], %2, [%3];"
                 :: "r"(dst), "l"(src), "r"(bytes), "r"(mbar) : "memory");
}
__device__ __forceinline__ void mbar_wait(uint32_t m, uint32_t ph) {
    uint32_t done;
    asm volatile("{\n\t.reg .pred p;\n\t"
                 "mbarrier.try_wait.parity.acquire.cta.shared::cta.b64 p, [%1], %2;\n\t"
                 "selp.b32 %0, 1, 0, p;\n\t}"
                 : "=r"(done) : "r"(m), "r"(ph) : "memory");
    if (!done) {
        asm volatile("{\n\t.reg .pred P1;\n\t"
                     "W_%=:\n\t"
                     "mbarrier.try_wait.parity.acquire.cta.shared::cta.b64 P1, [%0], %1, 0x989680;\n\t"
                     "@P1 bra.uni D_%=;\n\t"
                     "bra.uni W_%=;\n\t"
                     "D_%=:\n\t}"
                     :: "r"(m), "r"(ph) : "memory");
    }
}

// Monotonic grid barrier (all NCTA CTAs co-resident; grid = 148 = 1/SM).
__device__ __forceinline__ void grid_bar() {
    __syncthreads();
    if (threadIdx.x == 0) {
        __threadfence();
        int ticket = atomicAdd(&g_bar, 1);
        int target = (ticket / NCTA + 1) * NCTA;
        while (*(volatile int*)&g_bar < target) __nanosleep(64);
        __threadfence();
    }
    __syncthreads();
}

__device__ __forceinline__ bool valid1(int j) {
    int r = j / W1, c = j % W1;
    return (r >= BR) & (r < H1 - BR) & (c >= BR) & (c < W1 - BR);
}

// flush per-thread colmax accumulators for batch n via fire-and-forget RED.MAX
__device__ __forceinline__ void flush_cols(int n, int t, bool tail,
                                           float4 z0, float4 z1, float4 z2) {
    unsigned* cm = &g_colmax[n * SS + 4*t];
    atomicMax(cm+0, __float_as_uint(z0.x)); atomicMax(cm+1, __float_as_uint(z0.y));
    atomicMax(cm+2, __float_as_uint(z0.z)); atomicMax(cm+3, __float_as_uint(z0.w));
    cm += 4*TPB;
    atomicMax(cm+0, __float_as_uint(z1.x)); atomicMax(cm+1, __float_as_uint(z1.y));
    atomicMax(cm+2, __float_as_uint(z1.z)); atomicMax(cm+3, __float_as_uint(z1.w));
    if (tail) {
        cm += 4*TPB;
        atomicMax(cm+0, __float_as_uint(z2.x)); atomicMax(cm+1, __float_as_uint(z2.y));
        atomicMax(cm+2, __float_as_uint(z2.z)); atomicMax(cm+3, __float_as_uint(z2.w));
    }
}

__global__ __launch_bounds__(TPB) void fused(const float* __restrict__ conf,
                                             float* __restrict__ out) {
    extern __shared__ __align__(16) unsigned char smem[];
    __shared__ int   s_uring[DEPTH];
    __shared__ int   s_list[PH3ROWS];
    __shared__ float s_m[PH3ROWS];
    __shared__ int s_nl;
    __shared__ unsigned s_best;

    const int cid = blockIdx.x;        // 0..147
    const int t = threadIdx.x;
    const int warp = t >> 5, lane = t & 31;
    const bool tail = t < TAILQ;       // t < 176

    float4* tiles = (float4*)(smem + SM_TILES);
    float*  spmax = (float*)(smem + SM_PMAX);
    int*    spcnt = (int*)(smem + SM_PCNT);
    int*    spidx = (int*)(smem + SM_PIDX);
    const uint32_t sbase = smem_u32(smem);
    const uint32_t mb0   = sbase + SM_MBAR;

    if (t == 0) {
        for (int s = 0; s < DEPTH; s++) mbar_init(mb0 + 8*s, 1);
        asm volatile("fence.proxy.async.shared::cta;" ::: "memory");
    }
    __syncthreads();

    // ---- prologue: t0 claims up to DEPTH units, fills the ring ----
    bool stopped = false;              // meaningful on t0 only
    if (t == 0) {
        for (int s = 0; s < DEPTH; s++) {
            int u = -1;
            if (!stopped) {
                int tk = atomicAdd(&g_q, 1);
                int uu = tk % TICKETS;
                if (uu < NUNITS) u = uu; else stopped = true;
            }
            s_uring[s] = u;
            if (u >= 0) {
                mbar_expect_tx(mb0 + 8*s, STAGEB);
                bulk_ldg(sbase + s*STAGEB, (const char*)conf + (size_t)u * STAGEB, STAGEB, mb0 + 8*s);
            }
        }
    }
    __syncthreads();

    // ---- phase 1: work-stealing stream + reduce ----
    float4 z0 = {0,0,0,0}, z1 = {0,0,0,0}, z2 = {0,0,0,0};
    int cur_n = -1;
    int slot = 0, ph = 0;

    for (;;) {
        const int u = s_uring[slot];
        if (u < 0) break;
        const int un  = u / NSTAGES_PER_N;
        const int ust = u % NSTAGES_PER_N;

        if (un != cur_n) {             // n transition (<=3 per CTA; claim order is monotonic)
            if (cur_n >= 0) {
                flush_cols(cur_n, t, tail, z0, z1, z2);
                z0 = make_float4(0,0,0,0); z1 = make_float4(0,0,0,0); z2 = make_float4(0,0,0,0);
            }
            cur_n = un;
        }

        mbar_wait(mb0 + 8*slot, ph);

#pragma unroll
        for (int rr = 0; rr < RPS; rr++) {
            const float4* tp = tiles + (slot * RPS + rr) * NQ + t;
            float4 a0 = tp[0];
            float4 a1 = tp[TPB];
            float4 a2 = tail ? tp[2*TPB] : make_float4(0.f,0.f,0.f,0.f);

            z0.x = fmaxf(z0.x, a0.x); z0.y = fmaxf(z0.y, a0.y);
            z0.z = fmaxf(z0.z, a0.z); z0.w = fmaxf(z0.w, a0.w);
            z1.x = fmaxf(z1.x, a1.x); z1.y = fmaxf(z1.y, a1.y);
            z1.z = fmaxf(z1.z, a1.z); z1.w = fmaxf(z1.w, a1.w);
            z2.x = fmaxf(z2.x, a2.x); z2.y = fmaxf(z2.y, a2.y);
            z2.z = fmaxf(z2.z, a2.z); z2.w = fmaxf(z2.w, a2.w);

            float4 rm;
            rm.x = fmaxf(fmaxf(a0.x, a1.x), a2.x);
            rm.y = fmaxf(fmaxf(a0.y, a1.y), a2.y);
            rm.z = fmaxf(fmaxf(a0.z, a1.z), a2.z);
            rm.w = fmaxf(fmaxf(a0.w, a1.w), a2.w);
            float tm = fmaxf(fmaxf(rm.x, rm.y), fmaxf(rm.z, rm.w));

            float wm = __uint_as_float(__reduce_max_sync(0xffffffffu, __float_as_uint(tm)));

            unsigned mm =
                  (unsigned)(a0.x == wm)        | ((unsigned)(a0.y == wm) << 1)
                | ((unsigned)(a0.z == wm) << 2) | ((unsigned)(a0.w == wm) << 3)
                | ((unsigned)(a1.x == wm) << 4) | ((unsigned)(a1.y == wm) << 5)
                | ((unsigned)(a1.z == wm) << 6) | ((unsigned)(a1.w == wm) << 7)
                | ((unsigned)(a2.x == wm) << 8) | ((unsigned)(a2.y == wm) << 9)
                | ((unsigned)(a2.z == wm) <<10) | ((unsigned)(a2.w == wm) <<11);
            unsigned lcnt = (unsigned)__popc(mm);
            unsigned lidx = 0x7fffffffu;
            if (mm) {
                int bit = __ffs(mm) - 1;
                lidx = (unsigned)(4*t + ((bit >> 2) << 11) + (bit & 3));   // 2048 = 4*TPB
            }
            unsigned wcnt = __reduce_add_sync(0xffffffffu, lcnt);
            unsigned widx = __reduce_min_sync(0xffffffffu, lidx);
            if (lane == 0) {
                spmax[(slot*RPS + rr)*NW + warp] = wm;
                spcnt[(slot*RPS + rr)*NW + warp] = (int)wcnt;
                spidx[(slot*RPS + rr)*NW + warp] = (int)widx;
            }
        }

        __syncthreads();               // all warps done with tiles[slot] + spmax writes

        if (t < RPS) {                 // combine this unit's rows -> global
            float m = -1.f; int c = 0, ix = 0;
#pragma unroll
            for (int w = 0; w < NW; w++) {
                float om = spmax[(slot*RPS + t)*NW + w];
                if (om > m)       { m = om; c = spcnt[(slot*RPS + t)*NW + w]; ix = spidx[(slot*RPS + t)*NW + w]; }
                else if (om == m) { c += spcnt[(slot*RPS + t)*NW + w]; ix = min(ix, spidx[(slot*RPS + t)*NW + w]); }
            }
            size_t gi = (size_t)un * LL + ust * RPS + t;
            g_rowmax[gi] = m; g_rowj[gi] = ix; g_rowcnt[gi] = c;
        }

        if (t == 0) {                  // claim next unit into this slot
            int nu = -1;
            if (!stopped) {
                int tk = atomicAdd(&g_q, 1);
                int uu = tk % TICKETS;
                if (uu < NUNITS) nu = uu; else stopped = true;
            }
            s_uring[slot] = nu;
            if (nu >= 0) {
                mbar_expect_tx(mb0 + 8*slot, STAGEB);
                bulk_ldg(sbase + slot*STAGEB, (const char*)conf + (size_t)nu * STAGEB, STAGEB, mb0 + 8*slot);
            }
        }
        if (++slot == DEPTH) { slot = 0; ph ^= 1; }
    }

    if (cur_n >= 0) flush_cols(cur_n, t, tail, z0, z1, z2);
    if (t == 0) s_nl = 0;

    grid_bar();   // ---- colmax + row results complete everywhere ----

    // ---- phase 3: match rows [cid*130, +130) ----
    {
        const int gw = cid * PH3ROWS + t;
        const bool rowok = (t < PH3ROWS) && (gw < NL);

        float mconf = 0.f; int jid = 0; float mv = 0.f;
        bool need = false;
        float m = 0.f;
        if (rowok) {
            const int n = gw / LL, i = gw % LL;
            m = g_rowmax[gw];
            const int cnt = g_rowcnt[gw];
            const int jc  = g_rowj[gw];
            const int r0 = i / W0, c0 = i % W0;
            const bool v0 = (r0 >= BR) & (r0 < H0 - BR) & (c0 >= BR) & (c0 < W0 - BR);
            if (v0 && m > THRV) {
                if (valid1(jc) && g_colmax[n * SS + jc] == __float_as_uint(m)) {
                    mv = 1.f; jid = jc; mconf = m;
                } else if (cnt > 1) {
                    need = true;       // later tied position may pass -> exact rescan
                }
            }
        }
        if (need) { int p = atomicAdd(&s_nl, 1); s_list[p] = t; s_m[t] = m; }
        __syncthreads();
        if (rowok && !need) {
            out[gw]        = mconf;
            out[NL + gw]   = mv;
            out[2*NL + gw] = (float)jid;
        }

        const int nl = s_nl;
        for (int w = 0; w < nl; w++) {
            const int lrow = s_list[w];
            const int grow = cid * PH3ROWS + lrow;
            const int nn = grow / LL;
            const float mm = s_m[lrow];
            const float* rowp = conf + (size_t)grow * SS;
            if (t == 0) s_best = 0x7fffffffu;
            __syncthreads();
            float vv[RESCAN_K];        // preload all chunks first (MLP=10)
#pragma unroll
            for (int k = 0; k < RESCAN_K; k++) {
                int j = t + k * TPB;
                vv[k] = (j < SS) ? rowp[j] : -1.f;
            }
            unsigned lb = 0x7fffffffu;
#pragma unroll
            for (int k = 0; k < RESCAN_K; k++) {
                int j = t + k * TPB;
                if (j < SS && vv[k] == mm && valid1(j) && g_colmax[nn * SS + j] == __float_as_uint(vv[k]))
                    lb = min(lb, (unsigned)j);
            }
            if (lb != 0x7fffffffu) atomicMin(&s_best, lb);
            __syncthreads();
            if (t == 0) {
                unsigned bsel = s_best;
                bool hit = (bsel != 0x7fffffffu);
                out[grow]        = hit ? mm : 0.f;
                out[NL + grow]   = hit ? 1.f : 0.f;
                out[2*NL + grow] = hit ? (float)bsel : 0.f;
            }
            __syncthreads();
        }
    }

    grid_bar();   // ---- all colmax reads done ----

    // ---- phase 4: zero colmax for the next launch ----
    {
        int idx = cid * PH3ROWS + t;
        if (t < PH3ROWS && idx < NN*SS) g_colmax[idx] = 0u;
    }
}

extern "C" void kernel_launch(void* const* d_in, const int* in_sizes, int n_in,
                              void* d_out, int out_size) {
    const float* conf = (const float*)d_in[0];
    float* out = (float*)d_out;

    cudaFuncSetAttribute(fused, cudaFuncAttributeMaxDynamicSharedMemorySize, SMEM_REQ);
    fused<<<NCTA, TPB, SMEM_REQ>>>(conf, out);   // 148 CTAs = 1 per SM
}

// round 15
// speedup vs baseline: 1.2160x; 1.2160x over previous
#include <cuda_runtime.h>
#include <cstdint>
#include <cstddef>

// Problem constants (fixed by setup_inputs)
#define NN 4
#define H0 60
#define W0 80
#define H1 60
#define W1 80
#define LL (H0*W0)     // 4800 rows
#define SS (H1*W1)     // 4800 cols
#define NL (NN*LL)
#define THRV 0.2f
#define BR 2

#define TPB 512
#define NW (TPB/32)        // 16 warps
#define NQ (SS/4)          // 1200 float4 per row
#define ROWB (SS*4)        // 19200 bytes per row
#define RPS 2              // rows per stage
#define STAGEB (RPS*ROWB)  // 38400
#define DEPTH 5            // pipeline stages
#define NCTA 148           // 1 CTA per SM, all co-resident
#define TAILQ (NQ - 2*TPB) // 176: threads with a 3rd float4

#define NSTAGES 9600                // total 2-row stages (all batches)
#define NSTAGES_PER_N 2400
#define SPAN 8                      // stages per ticket (16 rows, 307KB sequential)
#define NSPANS (NSTAGES/SPAN)       // 1200 work tickets
#define TICKETS (NSPANS + NCTA)     // 1348 tickets consumed per launch, exactly
#define PH3ROWS 130                 // ceil(19200/148)
#define RESCAN_K 10                 // ceil(4800/512)

// smem layout (dynamic)
#define SM_TILES 0                        // DEPTH*STAGEB = 192000
#define SM_PMAX  (DEPTH*STAGEB)
#define SM_PCNT  (SM_PMAX + DEPTH*RPS*NW*4)
#define SM_PIDX  (SM_PCNT + DEPTH*RPS*NW*4)
#define SM_MBAR  (SM_PIDX + DEPTH*RPS*NW*4)
#define SMEM_REQ 194048

// Scratch (no allocations allowed).
// g_colmax: zero at entry (module init first run; phase-4 zeroing afterwards).
// g_q / g_bar: MONOTONIC counters, never reset; each launch consumes exactly
// 1348 work tickets and 2*148 barrier tickets -> replay-safe.
__device__ unsigned g_colmax[NN*SS];
__device__ float    g_rowmax[NL];
__device__ int      g_rowj[NL];
__device__ int      g_rowcnt[NL];
__device__ int      g_q;
__device__ int      g_bar;

__device__ __forceinline__ uint32_t smem_u32(const void* p) {
    uint32_t a;
    asm("{ .reg .u64 t; cvta.to.shared.u64 t, %1; cvt.u32.u64 %0, t; }" : "=r"(a) : "l"(p));
    return a;
}
__device__ __forceinline__ void mbar_init(uint32_t m, uint32_t cnt) {
    asm volatile("mbarrier.init.shared.b64 [%0], %1;" :: "r"(m), "r"(cnt) : "memory");
}
__device__ __forceinline__ void mbar_expect_tx(uint32_t m, uint32_t bytes) {
    asm volatile("mbarrier.arrive.expect_tx.shared.b64 _, [%0], %1;" :: "r"(m), "r"(bytes) : "memory");
}
__device__ __forceinline__ void bulk_ldg(uint32_t dst, const void* src, uint32_t bytes, uint32_t mbar) {
    asm volatile("cp.async.bulk.shared::cluster.global.mbarrier::complete_tx::bytes [%0], [%1], %2, [%3];"
                 :: "r"(dst), "l"(src), "r"(bytes), "r"(mbar) : "memory");
}
__device__ __forceinline__ void mbar_wait(uint32_t m, uint32_t ph) {
    uint32_t done;
    asm volatile("{\n\t.reg .pred p;\n\t"
                 "mbarrier.try_wait.parity.acquire.cta.shared::cta.b64 p, [%1], %2;\n\t"
                 "selp.b32 %0, 1, 0, p;\n\t}"
                 : "=r"(done) : "r"(m), "r"(ph) : "memory");
    if (!done) {
        asm volatile("{\n\t.reg .pred P1;\n\t"
                     "W_%=:\n\t"
                     "mbarrier.try_wait.parity.acquire.cta.shared::cta.b64 P1, [%0], %1, 0x989680;\n\t"
                     "@P1 bra.uni D_%=;\n\t"
                     "bra.uni W_%=;\n\t"
                     "D_%=:\n\t}"
                     :: "r"(m), "r"(ph) : "memory");
    }
}

// Monotonic grid barrier (all NCTA CTAs co-resident; grid = 148 = 1/SM).
__device__ __forceinline__ void grid_bar() {
    __syncthreads();
    if (threadIdx.x == 0) {
        __threadfence();
        int ticket = atomicAdd(&g_bar, 1);
        int target = (ticket / NCTA + 1) * NCTA;
        while (*(volatile int*)&g_bar < target) __nanosleep(64);
        __threadfence();
    }
    __syncthreads();
}

__device__ __forceinline__ bool valid1(int j) {
    int r = j / W1, c = j % W1;
    return (r >= BR) & (r < H1 - BR) & (c >= BR) & (c < W1 - BR);
}

// flush per-thread colmax accumulators for batch n via fire-and-forget RED.MAX
// (distinct addresses within a CTA -> spread-addr atomic throughput; proven R8)
__device__ __forceinline__ void flush_cols(int n, int t, bool tail,
                                           float4 z0, float4 z1, float4 z2) {
    unsigned* cm = &g_colmax[n * SS + 4*t];
    atomicMax(cm+0, __float_as_uint(z0.x)); atomicMax(cm+1, __float_as_uint(z0.y));
    atomicMax(cm+2, __float_as_uint(z0.z)); atomicMax(cm+3, __float_as_uint(z0.w));
    cm += 4*TPB;
    atomicMax(cm+0, __float_as_uint(z1.x)); atomicMax(cm+1, __float_as_uint(z1.y));
    atomicMax(cm+2, __float_as_uint(z1.z)); atomicMax(cm+3, __float_as_uint(z1.w));
    if (tail) {
        cm += 4*TPB;
        atomicMax(cm+0, __float_as_uint(z2.x)); atomicMax(cm+1, __float_as_uint(z2.y));
        atomicMax(cm+2, __float_as_uint(z2.z)); atomicMax(cm+3, __float_as_uint(z2.w));
    }
}

__global__ __launch_bounds__(TPB) void fused(const float* __restrict__ conf,
                                             float* __restrict__ out) {
    extern __shared__ __align__(16) unsigned char smem[];
    __shared__ int   s_uring[DEPTH];
    __shared__ int   s_list[PH3ROWS];
    __shared__ float s_m[PH3ROWS];
    __shared__ int s_nl;
    __shared__ unsigned s_best;

    const int cid = blockIdx.x;        // 0..147
    const int t = threadIdx.x;
    const int warp = t >> 5, lane = t & 31;
    const bool tail = t < TAILQ;       // t < 176

    float4* tiles = (float4*)(smem + SM_TILES);
    float*  spmax = (float*)(smem + SM_PMAX);
    int*    spcnt = (int*)(smem + SM_PCNT);
    int*    spidx = (int*)(smem + SM_PIDX);
    const uint32_t sbase = smem_u32(smem);
    const uint32_t mb0   = sbase + SM_MBAR;

    if (t == 0) {
        for (int s = 0; s < DEPTH; s++) mbar_init(mb0 + 8*s, 1);
        asm volatile("fence.proxy.async.shared::cta;" ::: "memory");
    }
    __syncthreads();

    // ---- t0 claim state: span iterator over coarse tickets ----
    int span_next = 0, span_left = 0;
    bool stopped = false;              // meaningful on t0 only

    // prologue: fill the ring
    if (t == 0) {
        for (int s = 0; s < DEPTH; s++) {
            int u = -1;
            if (span_left == 0 && !stopped) {
                int tk = atomicAdd(&g_q, 1);
                int uu = tk % TICKETS;
                if (uu < NSPANS) { span_next = uu * SPAN; span_left = SPAN; }
                else stopped = true;
            }
            if (span_left > 0) { u = span_next++; span_left--; }
            s_uring[s] = u;
            if (u >= 0) {
                mbar_expect_tx(mb0 + 8*s, STAGEB);
                bulk_ldg(sbase + s*STAGEB, (const char*)conf + (size_t)u * STAGEB, STAGEB, mb0 + 8*s);
            }
        }
    }
    __syncthreads();

    // ---- phase 1: coarse-grained work stealing stream + reduce ----
    float4 z0 = {0,0,0,0}, z1 = {0,0,0,0}, z2 = {0,0,0,0};
    int cur_n = -1;
    int slot = 0, ph = 0;

    for (;;) {
        const int u = s_uring[slot];       // global stage id, rows [2u, 2u+2)
        if (u < 0) break;
        const int un = u / NSTAGES_PER_N;  // batch; non-decreasing per CTA

        if (un != cur_n) {
            if (cur_n >= 0) {
                flush_cols(cur_n, t, tail, z0, z1, z2);
                z0 = make_float4(0,0,0,0); z1 = make_float4(0,0,0,0); z2 = make_float4(0,0,0,0);
            }
            cur_n = un;
        }

        mbar_wait(mb0 + 8*slot, ph);

#pragma unroll
        for (int rr = 0; rr < RPS; rr++) {
            const float4* tp = tiles + (slot * RPS + rr) * NQ + t;
            float4 a0 = tp[0];
            float4 a1 = tp[TPB];
            float4 a2 = tail ? tp[2*TPB] : make_float4(0.f,0.f,0.f,0.f);

            z0.x = fmaxf(z0.x, a0.x); z0.y = fmaxf(z0.y, a0.y);
            z0.z = fmaxf(z0.z, a0.z); z0.w = fmaxf(z0.w, a0.w);
            z1.x = fmaxf(z1.x, a1.x); z1.y = fmaxf(z1.y, a1.y);
            z1.z = fmaxf(z1.z, a1.z); z1.w = fmaxf(z1.w, a1.w);
            z2.x = fmaxf(z2.x, a2.x); z2.y = fmaxf(z2.y, a2.y);
            z2.z = fmaxf(z2.z, a2.z); z2.w = fmaxf(z2.w, a2.w);

            float4 rm;
            rm.x = fmaxf(fmaxf(a0.x, a1.x), a2.x);
            rm.y = fmaxf(fmaxf(a0.y, a1.y), a2.y);
            rm.z = fmaxf(fmaxf(a0.z, a1.z), a2.z);
            rm.w = fmaxf(fmaxf(a0.w, a1.w), a2.w);
            float tm = fmaxf(fmaxf(rm.x, rm.y), fmaxf(rm.z, rm.w));

            float wm = __uint_as_float(__reduce_max_sync(0xffffffffu, __float_as_uint(tm)));

            unsigned mm =
                  (unsigned)(a0.x == wm)        | ((unsigned)(a0.y == wm) << 1)
                | ((unsigned)(a0.z == wm) << 2) | ((unsigned)(a0.w == wm) << 3)
                | ((unsigned)(a1.x == wm) << 4) | ((unsigned)(a1.y == wm) << 5)
                | ((unsigned)(a1.z == wm) << 6) | ((unsigned)(a1.w == wm) << 7)
                | ((unsigned)(a2.x == wm) << 8) | ((unsigned)(a2.y == wm) << 9)
                | ((unsigned)(a2.z == wm) <<10) | ((unsigned)(a2.w == wm) <<11);
            unsigned lcnt = (unsigned)__popc(mm);
            unsigned lidx = 0x7fffffffu;
            if (mm) {
                int bit = __ffs(mm) - 1;
                lidx = (unsigned)(4*t + ((bit >> 2) << 11) + (bit & 3));   // 2048 = 4*TPB
            }
            unsigned wcnt = __reduce_add_sync(0xffffffffu, lcnt);
            unsigned widx = __reduce_min_sync(0xffffffffu, lidx);
            if (lane == 0) {
                spmax[(slot*RPS + rr)*NW + warp] = wm;
                spcnt[(slot*RPS + rr)*NW + warp] = (int)wcnt;
                spidx[(slot*RPS + rr)*NW + warp] = (int)widx;
            }
        }

        __syncthreads();               // all warps done with tiles[slot] + spmax writes

        if (t < RPS) {                 // combine this stage's rows -> global
            float m = -1.f; int c = 0, ix = 0;
#pragma unroll
            for (int w = 0; w < NW; w++) {
                float om = spmax[(slot*RPS + t)*NW + w];
                if (om > m)       { m = om; c = spcnt[(slot*RPS + t)*NW + w]; ix = spidx[(slot*RPS + t)*NW + w]; }
                else if (om == m) { c += spcnt[(slot*RPS + t)*NW + w]; ix = min(ix, spidx[(slot*RPS + t)*NW + w]); }
            }
            size_t gi = (size_t)u * RPS + t;   // global row id
            g_rowmax[gi] = m; g_rowj[gi] = ix; g_rowcnt[gi] = c;
        }

        if (t == 0) {                  // refill this slot from the span iterator
            int nu = -1;
            if (span_left == 0 && !stopped) {
                int tk = atomicAdd(&g_q, 1);
                int uu = tk % TICKETS;
                if (uu < NSPANS) { span_next = uu * SPAN; span_left = SPAN; }
                else stopped = true;
            }
            if (span_left > 0) { nu = span_next++; span_left--; }
            s_uring[slot] = nu;
            if (nu >= 0) {
                mbar_expect_tx(mb0 + 8*slot, STAGEB);
                bulk_ldg(sbase + slot*STAGEB, (const char*)conf + (size_t)nu * STAGEB, STAGEB, mb0 + 8*slot);
            }
        }
        if (++slot == DEPTH) { slot = 0; ph ^= 1; }
    }

    if (cur_n >= 0) flush_cols(cur_n, t, tail, z0, z1, z2);
    if (t == 0) s_nl = 0;

    grid_bar();   // ---- colmax + row results complete everywhere ----

    // ---- phase 3: match rows [cid*130, +130) ----
    {
        const int gw = cid * PH3ROWS + t;
        const bool rowok = (t < PH3ROWS) && (gw < NL);

        float mconf = 0.f; int jid = 0; float mv = 0.f;
        bool need = false;
        float m = 0.f;
        if (rowok) {
            const int n = gw / LL, i = gw % LL;
            m = g_rowmax[gw];
            const int cnt = g_rowcnt[gw];
            const int jc  = g_rowj[gw];
            const int r0 = i / W0, c0 = i % W0;
            const bool v0 = (r0 >= BR) & (r0 < H0 - BR) & (c0 >= BR) & (c0 < W0 - BR);
            if (v0 && m > THRV) {
                if (valid1(jc) && g_colmax[n * SS + jc] == __float_as_uint(m)) {
                    mv = 1.f; jid = jc; mconf = m;
                } else if (cnt > 1) {
                    need = true;       // later tied position may pass -> exact rescan
                }
            }
        }
        if (need) { int p = atomicAdd(&s_nl, 1); s_list[p] = t; s_m[t] = m; }
        __syncthreads();
        if (rowok && !need) {
            out[gw]        = mconf;
            out[NL + gw]   = mv;
            out[2*NL + gw] = (float)jid;
        }

        const int nl = s_nl;
        for (int w = 0; w < nl; w++) {
            const int lrow = s_list[w];
            const int grow = cid * PH3ROWS + lrow;
            const int nn = grow / LL;
            const float mm = s_m[lrow];
            const float* rowp = conf + (size_t)grow * SS;
            if (t == 0) s_best = 0x7fffffffu;
            __syncthreads();
            float vv[RESCAN_K];        // preload all chunks first (MLP=10)
#pragma unroll
            for (int k = 0; k < RESCAN_K; k++) {
                int j = t + k * TPB;
                vv[k] = (j < SS) ? rowp[j] : -1.f;
            }
            unsigned lb = 0x7fffffffu;
#pragma unroll
            for (int k = 0; k < RESCAN_K; k++) {
                int j = t + k * TPB;
                if (j < SS && vv[k] == mm && valid1(j) && g_colmax[nn * SS + j] == __float_as_uint(vv[k]))
                    lb = min(lb, (unsigned)j);
            }
            if (lb != 0x7fffffffu) atomicMin(&s_best, lb);
            __syncthreads();
            if (t == 0) {
                unsigned bsel = s_best;
                bool hit = (bsel != 0x7fffffffu);
                out[grow]        = hit ? mm : 0.f;
                out[NL + grow]   = hit ? 1.f : 0.f;
                out[2*NL + grow] = hit ? (float)bsel : 0.f;
            }
            __syncthreads();
        }
    }

    grid_bar();   // ---- all colmax reads done ----

    // ---- phase 4: zero colmax for the next launch ----
    {
        int idx = cid * PH3ROWS + t;
        if (t < PH3ROWS && idx < NN*SS) g_colmax[idx] = 0u;
    }
}

extern "C" void kernel_launch(void* const* d_in, const int* in_sizes, int n_in,
                              void* d_out, int out_size) {
    const float* conf = (const float*)d_in[0];
    float* out = (float*)d_out;

    cudaFuncSetAttribute(fused, cudaFuncAttributeMaxDynamicSharedMemorySize, SMEM_REQ);
    fused<<<NCTA, TPB, SMEM_REQ>>>(conf, out);   // 148 CTAs = 1 per SM
}

// round 16
// speedup vs baseline: 1.9200x; 1.5789x over previous
#include <cuda_runtime.h>
#include <cstdint>
#include <cstddef>

// Problem constants (fixed by setup_inputs)
#define NN 4
#define H0 60
#define W0 80
#define H1 60
#define W1 80
#define LL (H0*W0)     // 4800 rows
#define SS (H1*W1)     // 4800 cols
#define NL (NN*LL)
#define THRV 0.2f
#define BR 2

#define TPB 512
#define NW (TPB/32)        // 16 warps
#define NQ (SS/4)          // 1200 float4 per row
#define ROWB (SS*4)        // 19200 bytes per row
#define RPS 2              // rows per pipeline stage
#define STAGEB (RPS*ROWB)  // 38400
#define DEPTH 5            // pipeline stages (10 rows in flight)
#define CTAS_PER_N 37      // 37*4 = 148 CTAs = 1 per SM (all co-resident)
#define NCTA 148
#define MAXROWS 130        // ceil(4800/37)
#define TAILQ (NQ - 2*TPB) // 176: threads with a 3rd float4
#define ZERO_PER_CTA 130   // ceil(19200/148)
#define RESCAN_K 10        // ceil(4800/512)

// smem layout (dynamic)
#define SM_TILES 0                          // DEPTH*STAGEB = 192000
#define SM_PMAX  (DEPTH*STAGEB)             // 192000
#define SM_PCNT  (SM_PMAX + MAXROWS*NW*4)   // 200320
#define SM_PIDX  (SM_PCNT + MAXROWS*NW*4)   // 208640
#define SM_MBAR  (SM_PIDX + MAXROWS*NW*4)   // 216960
#define SMEM_REQ 217088

// Scratch (no allocations allowed).
// g_colmax: zero at entry (module init on run 1; phase-4 zeroing of the
//   previous launch afterwards) -> deterministic across graph replays.
// g_bar: MONOTONIC ticket counter, never reset; each launch consumes exactly
//   2*148 tickets -> replay-safe.
__device__ unsigned g_colmax[NN*SS];
__device__ int      g_bar;

__device__ __forceinline__ uint32_t smem_u32(const void* p) {
    uint32_t a;
    asm("{ .reg .u64 t; cvta.to.shared.u64 t, %1; cvt.u32.u64 %0, t; }" : "=r"(a) : "l"(p));
    return a;
}
__device__ __forceinline__ void mbar_init(uint32_t m, uint32_t cnt) {
    asm volatile("mbarrier.init.shared.b64 [%0], %1;" :: "r"(m), "r"(cnt) : "memory");
}
__device__ __forceinline__ void mbar_expect_tx(uint32_t m, uint32_t bytes) {
    asm volatile("mbarrier.arrive.expect_tx.shared.b64 _, [%0], %1;" :: "r"(m), "r"(bytes) : "memory");
}
__device__ __forceinline__ void bulk_ldg(uint32_t dst, const void* src, uint32_t bytes, uint32_t mbar) {
    asm volatile("cp.async.bulk.shared::cluster.global.mbarrier::complete_tx::bytes [%0], [%1], %2, [%3];"
                 :: "r"(dst), "l"(src), "r"(bytes), "r"(mbar) : "memory");
}
__device__ __forceinline__ void mbar_wait(uint32_t m, uint32_t ph) {
    uint32_t done;
    asm volatile("{\n\t.reg .pred p;\n\t"
                 "mbarrier.try_wait.parity.acquire.cta.shared::cta.b64 p, [%1], %2;\n\t"
                 "selp.b32 %0, 1, 0, p;\n\t}"
                 : "=r"(done) : "r"(m), "r"(ph) : "memory");
    if (!done) {
        asm volatile("{\n\t.reg .pred P1;\n\t"
                     "W_%=:\n\t"
                     "mbarrier.try_wait.parity.acquire.cta.shared::cta.b64 P1, [%0], %1, 0x989680;\n\t"
                     "@P1 bra.uni D_%=;\n\t"
                     "bra.uni W_%=;\n\t"
                     "D_%=:\n\t}"
                     :: "r"(m), "r"(ph) : "memory");
    }
}

// Monotonic grid barrier (all NCTA CTAs co-resident; grid = 148 = 1/SM).
__device__ __forceinline__ void grid_bar() {
    __syncthreads();
    if (threadIdx.x == 0) {
        __threadfence();
        int ticket = atomicAdd(&g_bar, 1);
        int target = (ticket / NCTA + 1) * NCTA;
        while (*(volatile int*)&g_bar < target) __nanosleep(64);
        __threadfence();
    }
    __syncthreads();
}

__device__ __forceinline__ bool valid1(int j) {
    int r = j / W1, c = j % W1;
    return (r >= BR) & (r < H1 - BR) & (c >= BR) & (c < W1 - BR);
}

__global__ __launch_bounds__(TPB) void fused(const float* __restrict__ conf,
                                             float* __restrict__ out) {
    extern __shared__ __align__(16) unsigned char smem[];
    __shared__ int   s_list[MAXROWS];
    __shared__ float s_m[MAXROWS];
    __shared__ int s_nl;
    __shared__ unsigned s_best;

    const int b = blockIdx.x;          // 0..36
    const int n = blockIdx.y;          // 0..3
    const int t = threadIdx.x;
    const int warp = t >> 5, lane = t & 31;
    const bool tail = t < TAILQ;       // t < 176

    const int rstart = (b * 4800) / CTAS_PER_N;
    const int rend   = ((b + 1) * 4800) / CTAS_PER_N;
    const int nrows  = rend - rstart;     // 129 or 130
    const int nstages = (nrows + RPS - 1) / RPS;
    const size_t grow0 = (size_t)n * LL + rstart;

    float4* tiles = (float4*)(smem + SM_TILES);
    float*  spmax = (float*)(smem + SM_PMAX);
    int*    spcnt = (int*)(smem + SM_PCNT);
    int*    spidx = (int*)(smem + SM_PIDX);
    const uint32_t sbase = smem_u32(smem);
    const uint32_t mb0   = sbase + SM_MBAR;

    // ---------------- Phase 1: stream + reduce (R8/R13-proven pipeline) ------
    if (t == 0) {
        for (int s = 0; s < DEPTH; s++) mbar_init(mb0 + 8*s, 1);
        asm volatile("fence.proxy.async.shared::cta;" ::: "memory");
    }
    __syncthreads();
    if (t == 0) {
        // stage s covers rows [s*RPS, s*RPS+1]; always load 2 full rows (odd-nrows
        // CTAs read 1 unused in-bounds row; the global-last CTA has even nrows).
        for (int s = 0; s < DEPTH; s++) {
            mbar_expect_tx(mb0 + 8*s, STAGEB);
            bulk_ldg(sbase + s*STAGEB, (const char*)conf + (grow0 + s*RPS) * ROWB, STAGEB, mb0 + 8*s);
        }
    }

    float4 z0 = {0,0,0,0}, z1 = {0,0,0,0}, z2 = {0,0,0,0};   // colmax accumulators

    int stage = 0, ph = 0;
    for (int s = 0; s < nstages; s++) {
        mbar_wait(mb0 + 8*stage, ph);

#pragma unroll
        for (int rr = 0; rr < RPS; rr++) {
            const int r = s * RPS + rr;
            if (r >= nrows) break;

            const float4* tp = tiles + (stage * RPS + rr) * NQ + t;
            float4 a0 = tp[0];
            float4 a1 = tp[TPB];
            float4 a2 = tail ? tp[2*TPB] : make_float4(0.f,0.f,0.f,0.f);

            z0.x = fmaxf(z0.x, a0.x); z0.y = fmaxf(z0.y, a0.y);
            z0.z = fmaxf(z0.z, a0.z); z0.w = fmaxf(z0.w, a0.w);
            z1.x = fmaxf(z1.x, a1.x); z1.y = fmaxf(z1.y, a1.y);
            z1.z = fmaxf(z1.z, a1.z); z1.w = fmaxf(z1.w, a1.w);
            z2.x = fmaxf(z2.x, a2.x); z2.y = fmaxf(z2.y, a2.y);
            z2.z = fmaxf(z2.z, a2.z); z2.w = fmaxf(z2.w, a2.w);

            float4 rm;
            rm.x = fmaxf(fmaxf(a0.x, a1.x), a2.x);
            rm.y = fmaxf(fmaxf(a0.y, a1.y), a2.y);
            rm.z = fmaxf(fmaxf(a0.z, a1.z), a2.z);
            rm.w = fmaxf(fmaxf(a0.w, a1.w), a2.w);
            float tm = fmaxf(fmaxf(rm.x, rm.y), fmaxf(rm.z, rm.w));

            float wm = __uint_as_float(__reduce_max_sync(0xffffffffu, __float_as_uint(tm)));

            // branch-free tie detection: 12-bit equality mask, monotonic in j
            unsigned mm =
                  (unsigned)(a0.x == wm)        | ((unsigned)(a0.y == wm) << 1)
                | ((unsigned)(a0.z == wm) << 2) | ((unsigned)(a0.w == wm) << 3)
                | ((unsigned)(a1.x == wm) << 4) | ((unsigned)(a1.y == wm) << 5)
                | ((unsigned)(a1.z == wm) << 6) | ((unsigned)(a1.w == wm) << 7)
                | ((unsigned)(a2.x == wm) << 8) | ((unsigned)(a2.y == wm) << 9)
                | ((unsigned)(a2.z == wm) <<10) | ((unsigned)(a2.w == wm) <<11);
            unsigned lcnt = (unsigned)__popc(mm);
            unsigned lidx = 0x7fffffffu;
            if (mm) {
                int bit = __ffs(mm) - 1;
                lidx = (unsigned)(4*t + ((bit >> 2) << 11) + (bit & 3));  // 2048 = 4*TPB
            }
            unsigned wcnt = __reduce_add_sync(0xffffffffu, lcnt);
            unsigned widx = __reduce_min_sync(0xffffffffu, lidx);
            if (lane == 0) {
                spmax[r*NW + warp] = wm;
                spcnt[r*NW + warp] = (int)wcnt;
                spidx[r*NW + warp] = (int)widx;
            }
        }

        __syncthreads();                 // everyone done reading tiles[stage]
        int sn = s + DEPTH;
        if (t == 0 && sn * RPS < nrows) {
            mbar_expect_tx(mb0 + 8*stage, STAGEB);
            bulk_ldg(sbase + stage*STAGEB, (const char*)conf + (grow0 + sn*RPS) * ROWB, STAGEB, mb0 + 8*stage);
        }
        if (++stage == DEPTH) { stage = 0; ph ^= 1; }
    }
    __syncthreads();

    // per-row combine -> REGISTERS (this CTA matches its own rows later)
    float rowm = -1.f; int rowc = 0, rowi = 0;
    if (t < nrows) {
#pragma unroll
        for (int w = 0; w < NW; w++) {
            float om = spmax[t*NW + w];
            if (om > rowm)       { rowm = om; rowc = spcnt[t*NW + w]; rowi = spidx[t*NW + w]; }
            else if (om == rowm) { rowc += spcnt[t*NW + w]; rowi = min(rowi, spidx[t*NW + w]); }
        }
    }

    // flush colmax accumulators: spread-address fire-and-forget RED.MAX (R8-proven)
    {
        unsigned* cm = &g_colmax[n * SS + 4*t];
        atomicMax(cm+0, __float_as_uint(z0.x)); atomicMax(cm+1, __float_as_uint(z0.y));
        atomicMax(cm+2, __float_as_uint(z0.z)); atomicMax(cm+3, __float_as_uint(z0.w));
        cm += 4*TPB;
        atomicMax(cm+0, __float_as_uint(z1.x)); atomicMax(cm+1, __float_as_uint(z1.y));
        atomicMax(cm+2, __float_as_uint(z1.z)); atomicMax(cm+3, __float_as_uint(z1.w));
        if (tail) {
            cm += 4*TPB;
            atomicMax(cm+0, __float_as_uint(z2.x)); atomicMax(cm+1, __float_as_uint(z2.y));
            atomicMax(cm+2, __float_as_uint(z2.z)); atomicMax(cm+3, __float_as_uint(z2.w));
        }
    }
    if (t == 0) s_nl = 0;

    grid_bar();   // ---- all colmax atomics complete everywhere ----

    // ---------------- Phase 3: match this CTA's own rows ---------------------
    {
        float mconf = 0.f; int jid = 0; float mv = 0.f;
        bool need = false;
        if (t < nrows) {
            const int i = rstart + t;                   // row within batch n
            const int r0 = i / W0, c0 = i % W0;
            const bool v0 = (r0 >= BR) & (r0 < H0 - BR) & (c0 >= BR) & (c0 < W0 - BR);
            if (v0 && rowm > THRV) {
                // rowi = global min-index of the row max; if it passes the mask
                // it is the first True regardless of ties.
                if (valid1(rowi) && g_colmax[n * SS + rowi] == __float_as_uint(rowm)) {
                    mv = 1.f; jid = rowi; mconf = rowm;
                } else if (rowc > 1) {
                    need = true;     // a later tied position may pass -> rescan
                }
            }
        }
        if (need) { int p = atomicAdd(&s_nl, 1); s_list[p] = t; s_m[t] = rowm; }
        __syncthreads();
        if (t < nrows && !need) {
            const size_t gw = grow0 + t;
            out[gw]        = mconf;
            out[NL + gw]   = mv;
            out[2*NL + gw] = (float)jid;
        }

        const int nl = s_nl;
        for (int w = 0; w < nl; w++) {
            const int lrow = s_list[w];
            const float mm = s_m[lrow];
            const float* rowp = conf + (grow0 + lrow) * SS;
            if (t == 0) s_best = 0x7fffffffu;
            __syncthreads();
            float vv[RESCAN_K];        // preload all chunks first (MLP=10)
#pragma unroll
            for (int k = 0; k < RESCAN_K; k++) {
                int j = t + k * TPB;
                vv[k] = (j < SS) ? rowp[j] : -1.f;
            }
            unsigned lb = 0x7fffffffu;
#pragma unroll
            for (int k = 0; k < RESCAN_K; k++) {
                int j = t + k * TPB;
                if (j < SS && vv[k] == mm && valid1(j) && g_colmax[n * SS + j] == __float_as_uint(vv[k]))
                    lb = min(lb, (unsigned)j);
            }
            if (lb != 0x7fffffffu) atomicMin(&s_best, lb);
            __syncthreads();
            if (t == 0) {
                unsigned bsel = s_best;
                bool hit = (bsel != 0x7fffffffu);
                const size_t gw = grow0 + lrow;
                out[gw]        = hit ? mm : 0.f;
                out[NL + gw]   = hit ? 1.f : 0.f;
                out[2*NL + gw] = hit ? (float)bsel : 0.f;
            }
            __syncthreads();
        }
    }

    grid_bar();   // ---- all colmax reads done ----

    // ---------------- Phase 4: zero colmax for the next launch ---------------
    {
        int idx = (n * CTAS_PER_N + b) * ZERO_PER_CTA + t;
        if (t < ZERO_PER_CTA && idx < NN*SS) g_colmax[idx] = 0u;
    }
}

extern "C" void kernel_launch(void* const* d_in, const int* in_sizes, int n_in,
                              void* d_out, int out_size) {
    const float* conf = (const float*)d_in[0];
    float* out = (float*)d_out;

    cudaFuncSetAttribute(fused, cudaFuncAttributeMaxDynamicSharedMemorySize, SMEM_REQ);
    dim3 g1(CTAS_PER_N, NN);          // 37 x 4 = 148 CTAs = exactly 1 per SM
    fused<<<g1, TPB, SMEM_REQ>>>(conf, out);
}